// round 2
// baseline (speedup 1.0000x reference)
#include <cuda_runtime.h>
#include <math.h>

#define TOKENS 16384
#define Dm 2048
#define Em 128
#define Hm 128
#define MT 64          // tokens per CTA
#define KC 32          // k-chunk
#define NCHUNK (Dm / KC)
#define XS_STRIDE 36   // padded row stride for xs (16B aligned, conflict-free)
#define WDT_STRIDE 132 // padded row stride for decoder weight in smem

// Pre-transposed weights (device scratch; no dynamic allocation allowed)
__device__ float g_WrT[Dm * Em];  // [k][e]
__device__ float g_WdT[Em * Hm];  // [e][h]

__device__ __forceinline__ unsigned long long pk2(float x, float y) {
    unsigned long long r;
    asm("mov.b64 %0, {%1, %2};" : "=l"(r) : "f"(x), "f"(y));
    return r;
}
__device__ __forceinline__ void fma2(unsigned long long& d, unsigned long long a, unsigned long long b) {
    asm("fma.rn.f32x2 %0, %1, %2, %0;" : "+l"(d) : "l"(a), "l"(b));
}
__device__ __forceinline__ float2 up2(unsigned long long v) {
    float2 r;
    asm("mov.b64 {%0, %1}, %2;" : "=f"(r.x), "=f"(r.y) : "l"(v));
    return r;
}

// Generic 32x32 tiled transpose: in[R][C] -> out[C][R]
__global__ void tr_kernel(const float* __restrict__ in, float* __restrict__ out, int R, int C) {
    __shared__ float tile[32][33];
    int x = blockIdx.x * 32 + threadIdx.x;
#pragma unroll
    for (int j = 0; j < 32; j += 8) {
        int y = blockIdx.y * 32 + threadIdx.y + j;
        if (y < R && x < C) tile[threadIdx.y + j][threadIdx.x] = in[(size_t)y * C + x];
    }
    __syncthreads();
    int x2 = blockIdx.y * 32 + threadIdx.x;
#pragma unroll
    for (int j = 0; j < 32; j += 8) {
        int y2 = blockIdx.x * 32 + threadIdx.y + j;
        if (y2 < C && x2 < R) out[(size_t)y2 * R + x2] = tile[threadIdx.x][threadIdx.y + j];
    }
}

struct SmemLayout {
    union {
        struct {
            float xs[MT * XS_STRIDE];   // 9216 B
            float ws[KC * Em];          // 16384 B
        } g;
        float emb[MT * Em];             // 32768 B
    } u;
    float wdt[Em * WDT_STRIDE];         // 67584 B
    float gbuf[8 * Hm];                 // 4096 B
    float abuf[8 * Hm];                 // 4096 B
    float rnn[Em];
    float gam[Em];
    float bet[Em];
};

__global__ __launch_bounds__(256) void fused_kernel(
    const float* __restrict__ x,
    const float* __restrict__ gumbel,
    const float* __restrict__ rnn_g,
    const float* __restrict__ gamma_g,
    const float* __restrict__ beta_g,
    const int* __restrict__ topk_p,
    float* __restrict__ out_bin,
    float* __restrict__ out_ap)
{
    extern __shared__ char smraw[];
    SmemLayout* sm = reinterpret_cast<SmemLayout*>(smraw);
    const int tid = threadIdx.x;
    const int t0 = blockIdx.x * MT;

    // ---- stage decoder weight + LN params into smem ----
#pragma unroll
    for (int p = 0; p < 16; p++) {
        int n = tid + 256 * p;
        int e = n >> 5;
        int h4 = (n & 31) * 4;
        *(float4*)&sm->wdt[e * WDT_STRIDE + h4] = *(const float4*)&g_WdT[e * Hm + h4];
    }
    if (tid < 128) {
        sm->rnn[tid] = rnn_g[tid];
        sm->gam[tid] = gamma_g[tid];
        sm->bet[tid] = beta_g[tid];
    }

    // ---- GEMM1: acc[r][e] = sum_k x[t0+r][k] * Wr[e][k] ----
    const int c0 = tid & 15;  // col group: cols c0*8 .. c0*8+7
    const int rg = tid >> 4;  // row group: rows rg*4 .. rg*4+3
    const int r0 = rg * 4;

    unsigned long long acc[4][4];
#pragma unroll
    for (int i = 0; i < 4; i++)
#pragma unroll
        for (int j = 0; j < 4; j++) acc[i][j] = 0ull;

    // global-load mappings (prefetch into regs, then STS.128)
    const int xr = tid >> 3;          // 0..31 (two passes: +0, +32)
    const int xc4 = (tid & 7) * 4;    // k offset within chunk
    const int wc4 = (tid & 31) * 4;   // e offset

    float4 xf[2], wf[4];
    {
        const float* xg = x + (size_t)t0 * Dm;
#pragma unroll
        for (int p = 0; p < 2; p++)
            xf[p] = *(const float4*)&xg[(size_t)(xr + 32 * p) * Dm + xc4];
#pragma unroll
        for (int p = 0; p < 4; p++) {
            int wk = (tid + 256 * p) >> 5;
            wf[p] = *(const float4*)&g_WrT[wk * Em + wc4];
        }
    }

    for (int ch = 0; ch < NCHUNK; ++ch) {
        __syncthreads();
#pragma unroll
        for (int p = 0; p < 2; p++)
            *(float4*)&sm->u.g.xs[(xr + 32 * p) * XS_STRIDE + xc4] = xf[p];
#pragma unroll
        for (int p = 0; p < 4; p++) {
            int wk = (tid + 256 * p) >> 5;
            *(float4*)&sm->u.g.ws[wk * Em + wc4] = wf[p];
        }
        __syncthreads();

        if (ch + 1 < NCHUNK) {
            const int k0 = (ch + 1) * KC;
            const float* xg = x + (size_t)t0 * Dm + k0;
#pragma unroll
            for (int p = 0; p < 2; p++)
                xf[p] = *(const float4*)&xg[(size_t)(xr + 32 * p) * Dm + xc4];
#pragma unroll
            for (int p = 0; p < 4; p++) {
                int wk = (tid + 256 * p) >> 5;
                wf[p] = *(const float4*)&g_WrT[(k0 + wk) * Em + wc4];
            }
        }

#pragma unroll
        for (int kk = 0; kk < KC; kk += 4) {
            float4 xv[4];
#pragma unroll
            for (int i = 0; i < 4; i++)
                xv[i] = *(const float4*)&sm->u.g.xs[(r0 + i) * XS_STRIDE + kk];
#pragma unroll
            for (int q = 0; q < 4; q++) {
                ulonglong2 w01 = *(const ulonglong2*)&sm->u.g.ws[(kk + q) * Em + c0 * 8];
                ulonglong2 w23 = *(const ulonglong2*)&sm->u.g.ws[(kk + q) * Em + c0 * 8 + 4];
#pragma unroll
                for (int i = 0; i < 4; i++) {
                    float a = (q == 0) ? xv[i].x : (q == 1) ? xv[i].y : (q == 2) ? xv[i].z : xv[i].w;
                    unsigned long long a2 = pk2(a, a);
                    fma2(acc[i][0], a2, w01.x);
                    fma2(acc[i][1], a2, w01.y);
                    fma2(acc[i][2], a2, w23.x);
                    fma2(acc[i][3], a2, w23.y);
                }
            }
        }
    }

    __syncthreads();  // done reading xs/ws; emb aliases them
#pragma unroll
    for (int i = 0; i < 4; i++)
#pragma unroll
        for (int j = 0; j < 4; j++) {
            float2 v = up2(acc[i][j]);
            *(float2*)&sm->u.emb[(r0 + i) * Em + c0 * 8 + j * 2] = v;
        }
    __syncthreads();

    // ---- Phase 2: per-token LN -> GELU -> decoder -> gumbel-sigmoid -> mask ----
    const int w = tid >> 5;
    const int lane = tid & 31;
    const int K = *topk_p;
    const float Kf = (float)K;

    for (int tt = 0; tt < 8; ++tt) {
        const int t = w * 8 + tt;
        const int gt = t0 + t;

        float v[4];
#pragma unroll
        for (int j = 0; j < 4; j++) {
            int e = lane + 32 * j;
            v[j] = sm->u.emb[t * Em + e] + sm->rnn[e];
        }
        float s = v[0] + v[1] + v[2] + v[3];
#pragma unroll
        for (int o = 16; o > 0; o >>= 1) s += __shfl_xor_sync(0xffffffffu, s, o);
        const float mu = s * (1.0f / 128.0f);
        float q = 0.f;
#pragma unroll
        for (int j = 0; j < 4; j++) { float d = v[j] - mu; q += d * d; }
#pragma unroll
        for (int o = 16; o > 0; o >>= 1) q += __shfl_xor_sync(0xffffffffu, q, o);
        const float inv = rsqrtf(q * (1.0f / 128.0f) + 1e-5f);

        __syncwarp();  // gbuf reuse fence (previous token's reads done)
#pragma unroll
        for (int j = 0; j < 4; j++) {
            int e = lane + 32 * j;
            float h = (v[j] - mu) * inv * sm->gam[e] + sm->bet[e];
            sm->gbuf[w * Hm + e] = 0.5f * h * (1.0f + erff(h * 0.70710678118654752f));
        }
        __syncwarp();

        // decoder: logits[h] = sum_e g[e] * Wd[h][e], h = lane*4 + jj
        unsigned long long l0 = 0ull, l1 = 0ull;
#pragma unroll 4
        for (int e = 0; e < Em; e++) {
            float a = sm->gbuf[w * Hm + e];
            unsigned long long a2 = pk2(a, a);
            ulonglong2 wd = *(const ulonglong2*)&sm->wdt[e * WDT_STRIDE + lane * 4];
            fma2(l0, a2, wd.x);
            fma2(l1, a2, wd.y);
        }
        float2 p0 = up2(l0), p1 = up2(l1);
        float lg[4] = {p0.x, p0.y, p1.x, p1.y};

        float4 gu = *(const float4*)&gumbel[(size_t)gt * Hm + lane * 4];
        float gua[4] = {gu.x, gu.y, gu.z, gu.w};

        float ap[4], bn[4];
        float csum = 0.f;
#pragma unroll
        for (int jj = 0; jj < 4; jj++) {
            float z = (lg[jj] + gua[jj] + 3.0f) * 2.5f;   // /0.4
            ap[jj] = 1.0f / (1.0f + expf(-z));
            bn[jj] = rintf(ap[jj]);                       // round-half-even, matches jnp.round
            csum += bn[jj];
        }
#pragma unroll
        for (int o = 16; o > 0; o >>= 1) csum += __shfl_xor_sync(0xffffffffu, csum, o);

        float ob[4];
        if (csum > Kf || csum == 0.0f) {      // warp-uniform branch
            const int kneed = (csum > Kf) ? K : 1;  // top-k mask or argmax fallback
#pragma unroll
            for (int jj = 0; jj < 4; jj++) sm->abuf[w * Hm + lane * 4 + jj] = ap[jj];
            __syncwarp();
            int r[4] = {0, 0, 0, 0};
            for (int j4 = 0; j4 < Hm; j4 += 4) {
                float4 av = *(const float4*)&sm->abuf[w * Hm + j4];
                float aj[4] = {av.x, av.y, av.z, av.w};
#pragma unroll
                for (int u = 0; u < 4; u++) {
                    int j = j4 + u;
#pragma unroll
                    for (int jj = 0; jj < 4; jj++) {
                        int idx = lane * 4 + jj;
                        // stable rank: (value desc, index asc) — matches lax.top_k / argmax
                        r[jj] += (aj[u] > ap[jj]) || (aj[u] == ap[jj] && j < idx);
                    }
                }
            }
#pragma unroll
            for (int jj = 0; jj < 4; jj++) ob[jj] = (r[jj] < kneed) ? 1.0f : 0.0f;
            __syncwarp();  // abuf reuse fence
        } else {
#pragma unroll
            for (int jj = 0; jj < 4; jj++) ob[jj] = bn[jj];
        }

        *(float4*)&out_bin[(size_t)gt * Hm + lane * 4] = make_float4(ob[0], ob[1], ob[2], ob[3]);
        if (out_ap)
            *(float4*)&out_ap[(size_t)gt * Hm + lane * 4] = make_float4(ap[0], ap[1], ap[2], ap[3]);
    }
}

extern "C" void kernel_launch(void* const* d_in, const int* in_sizes, int n_in,
                              void* d_out, int out_size) {
    const float* x        = (const float*)d_in[0];  // [B,S,D]
    const float* W_router = (const float*)d_in[1];  // [E,D]
    const float* W_dec    = (const float*)d_in[2];  // [H,E]
    const float* ln_gamma = (const float*)d_in[3];  // [E]
    const float* ln_beta  = (const float*)d_in[4];  // [E]
    const float* rnn      = (const float*)d_in[5];  // [E]
    const float* gumbel   = (const float*)d_in[6];  // [B,S,H]
    const int*   topk     = (const int*)d_in[7];    // scalar

    float* out_bin = (float*)d_out;
    const size_t N = (size_t)TOKENS * Hm;
    float* out_ap = ((size_t)out_size >= 2 * N) ? out_bin + N : nullptr;

    float *wrt_ptr = nullptr, *wdt_ptr = nullptr;
    cudaGetSymbolAddress((void**)&wrt_ptr, g_WrT);
    cudaGetSymbolAddress((void**)&wdt_ptr, g_WdT);

    // Pre-transpose weights so GEMM smem fills are coalesced + conflict-free.
    tr_kernel<<<dim3(Dm / 32, Em / 32), dim3(32, 8)>>>(W_router, wrt_ptr, Em, Dm);
    tr_kernel<<<dim3(Em / 32, Hm / 32), dim3(32, 8)>>>(W_dec, wdt_ptr, Hm, Em);

    const int smem_bytes = (int)sizeof(SmemLayout);
    cudaFuncSetAttribute(fused_kernel, cudaFuncAttributeMaxDynamicSharedMemorySize, smem_bytes);

    fused_kernel<<<TOKENS / MT, 256, smem_bytes>>>(
        x, gumbel, rnn, ln_gamma, ln_beta, topk, out_bin, out_ap);
}

// round 4
// speedup vs baseline: 1.3878x; 1.3878x over previous
#include <cuda_runtime.h>
#include <math.h>
#include <stdint.h>

#define TOKENS 16384
#define Dm 2048
#define Em 128
#define Hm 128
#define MT 128
#define KC 32
#define NCH 64
#define XSTR 132
#define WSTR 132

// float-index smem offsets
#define XS_F   0
#define WS_F   4224
#define EMB_F  0          // aliases GEMM region after GEMM
#define EMB_STR 132
#define WDT_F  16896      // beyond GEMM region: usable from kernel start
#define GBUF_F 33280
#define ABUF_F 34304
#define RNN_F  35328
#define GAM_F  35456
#define BET_F  35584
#define SMEM_SZ (35712 * 4 + 512)

__device__ float g_WrT[Dm * Em];   // [k][swizzled e-blocks]
__device__ float g_WdT[Em * Hm];   // [e][h]

typedef unsigned long long ull;

__device__ __forceinline__ void fma2(ull& d, ull a, ull b) {
    asm("fma.rn.f32x2 %0, %1, %2, %0;" : "+l"(d) : "l"(a), "l"(b));
}
__device__ __forceinline__ float2 up2(ull v) {
    float2 r; asm("mov.b64 {%0, %1}, %2;" : "=f"(r.x), "=f"(r.y) : "l"(v)); return r;
}
__device__ __forceinline__ ull pk2(float x, float y) {
    ull r; asm("mov.b64 %0, {%1, %2};" : "=l"(r) : "f"(x), "f"(y)); return r;
}
__device__ __forceinline__ ull swp(ull v) {
    float2 f = up2(v); return pk2(f.y, f.x);
}
__device__ __forceinline__ ull pk2d(float x) {
    ull r; asm("mov.b64 %0, {%1, %1};" : "=l"(r) : "f"(x)); return r;
}

// prep: W_router[e][k] -> g_WrT[k][sw(e-block)]; W_dec[h][e] -> g_WdT[e][h]
__global__ void prep_kernel(const float* __restrict__ Wr, const float* __restrict__ Wd) {
    int i = blockIdx.x * 256 + threadIdx.x;   // i over E*Dm, k fastest
    int e = i >> 11, k = i & (Dm - 1);
    int b = e >> 2;
    int sb = b ^ (b >> 3);                    // 16B-block swizzle, bijective on 0..31
    g_WrT[k * Em + sb * 4 + (e & 3)] = Wr[i];
    if (i < Em * Hm) g_WdT[(i & 127) * Hm + (i >> 7)] = Wd[i];
}

__global__ __launch_bounds__(256, 1) void fused_kernel(
    const float* __restrict__ x, const float* __restrict__ gumbel,
    const float* __restrict__ rnn_g, const float* __restrict__ gamma_g,
    const float* __restrict__ beta_g, const int* __restrict__ topk_p,
    float* __restrict__ out_bin, float* __restrict__ out_ap)
{
    extern __shared__ float fs[];
    const int tid = threadIdx.x;
    const int wid = tid >> 5;
    const int lane = tid & 31;
    const int t0 = blockIdx.x * MT;

    // ---- stage decoder weights + LN params (region disjoint from GEMM buffers) ----
#pragma unroll
    for (int p = 0; p < 16; p++) {
        int n = tid + 256 * p;                 // 4096 float4 = 16384 floats
        *(float4*)&fs[WDT_F + n * 4] = *(const float4*)&g_WdT[n * 4];
    }
    if (tid < 128) {
        fs[RNN_F + tid] = rnn_g[tid];
        fs[GAM_F + tid] = gamma_g[tid];
        fs[BET_F + tid] = beta_g[tid];
    }

    // ---- GEMM1: emb[128 tok][128 e], 8x8 per-thread diagonal-paired tiles ----
    const int tm = tid >> 4;      // 0..15 -> tokens 8*tm..
    const int te = tid & 15;      // 0..15 -> e 8*te..
    const int b0 = 2 * te, b1 = 2 * te + 1;
    const int s0 = b0 ^ (b0 >> 3), s1 = b1 ^ (b1 >> 3);
    const int aoff = XS_F + 8 * tm;
    const int boff0 = WS_F + 4 * s0;
    const int boff1 = WS_F + 4 * s1;

    ull accA[4][4], accB[4][4];
#pragma unroll
    for (int i = 0; i < 4; i++)
#pragma unroll
        for (int j = 0; j < 4; j++) { accA[i][j] = 0ull; accB[i][j] = 0ull; }

    float4 xf[4], wf[4];
    {
        const float* xg = x + (size_t)t0 * Dm;
#pragma unroll
        for (int p = 0; p < 4; p++) {
            int idx = tid + 256 * p;
            xf[p] = *(const float4*)&xg[(size_t)(idx >> 3) * Dm + (idx & 7) * 4];
        }
#pragma unroll
        for (int p = 0; p < 4; p++) {
            int idx = tid + 256 * p;
            wf[p] = *(const float4*)&g_WrT[(idx >> 5) * Em + (idx & 31) * 4];
        }
    }

    for (int ch = 0; ch < NCH; ++ch) {
        __syncthreads();
#pragma unroll
        for (int p = 0; p < 4; p++) {
            int idx = tid + 256 * p, m = idx >> 3, kq = (idx & 7) * 4;
            fs[XS_F + (kq + 0) * XSTR + m] = xf[p].x;
            fs[XS_F + (kq + 1) * XSTR + m] = xf[p].y;
            fs[XS_F + (kq + 2) * XSTR + m] = xf[p].z;
            fs[XS_F + (kq + 3) * XSTR + m] = xf[p].w;
        }
#pragma unroll
        for (int p = 0; p < 4; p++) {
            int idx = tid + 256 * p;
            *(float4*)&fs[WS_F + (idx >> 5) * WSTR + (idx & 31) * 4] = wf[p];
        }
        __syncthreads();

        if (ch + 1 < NCH) {
            const int k0 = (ch + 1) * KC;
            const float* xg = x + (size_t)t0 * Dm + k0;
#pragma unroll
            for (int p = 0; p < 4; p++) {
                int idx = tid + 256 * p;
                xf[p] = *(const float4*)&xg[(size_t)(idx >> 3) * Dm + (idx & 7) * 4];
            }
#pragma unroll
            for (int p = 0; p < 4; p++) {
                int idx = tid + 256 * p;
                wf[p] = *(const float4*)&g_WrT[(k0 + (idx >> 5)) * Em + (idx & 31) * 4];
            }
        }

#pragma unroll 8
        for (int k = 0; k < KC; ++k) {
            ulonglong2 A0 = *(const ulonglong2*)&fs[aoff + k * XSTR];
            ulonglong2 A1 = *(const ulonglong2*)&fs[aoff + k * XSTR + 4];
            ulonglong2 B0 = *(const ulonglong2*)&fs[boff0 + k * WSTR];
            ulonglong2 B1 = *(const ulonglong2*)&fs[boff1 + k * WSTR];
            ull ap[4] = {A0.x, A0.y, A1.x, A1.y};
            ull bp[4] = {B0.x, B0.y, B1.x, B1.y};
            ull sp[4] = {swp(B0.x), swp(B0.y), swp(B1.x), swp(B1.y)};
#pragma unroll
            for (int i = 0; i < 4; i++)
#pragma unroll
                for (int j = 0; j < 4; j++) {
                    fma2(accA[i][j], ap[i], bp[j]);
                    fma2(accB[i][j], ap[i], sp[j]);
                }
        }
    }

    __syncthreads();   // GEMM reads done; emb aliases xs/ws
#pragma unroll
    for (int i = 0; i < 4; i++)
#pragma unroll
        for (int j = 0; j < 4; j++) {
            float2 a = up2(accA[i][j]), b = up2(accB[i][j]);
            int m0 = 8 * tm + 2 * i, e0 = 8 * te + 2 * j;
            *(float2*)&fs[EMB_F + m0 * EMB_STR + e0]       = make_float2(a.x, b.x);
            *(float2*)&fs[EMB_F + (m0 + 1) * EMB_STR + e0] = make_float2(b.y, a.y);
        }
    __syncthreads();

    // ---- epilogue: LN -> GELU -> decoder -> gumbel-sigmoid -> top-k mask ----
    const int w = wid;
    const int K = *topk_p;
    const float Kf = (float)K;

    for (int tt = 0; tt < 16; ++tt) {
        const int t = w * 16 + tt;
        const int gt = t0 + t;

        float v[4];
#pragma unroll
        for (int j = 0; j < 4; j++) {
            int e = lane + 32 * j;
            v[j] = fs[EMB_F + t * EMB_STR + e] + fs[RNN_F + e];
        }
        float s = v[0] + v[1] + v[2] + v[3];
#pragma unroll
        for (int o = 16; o > 0; o >>= 1) s += __shfl_xor_sync(0xffffffffu, s, o);
        const float mu = s * (1.0f / 128.0f);
        float q = 0.f;
#pragma unroll
        for (int j = 0; j < 4; j++) { float d = v[j] - mu; q += d * d; }
#pragma unroll
        for (int o = 16; o > 0; o >>= 1) q += __shfl_xor_sync(0xffffffffu, q, o);
        const float inv = rsqrtf(q * (1.0f / 128.0f) + 1e-5f);

        __syncwarp();
#pragma unroll
        for (int j = 0; j < 4; j++) {
            int e = lane + 32 * j;
            float h = (v[j] - mu) * inv * fs[GAM_F + e] + fs[BET_F + e];
            fs[GBUF_F + w * Hm + e] = 0.5f * h * (1.0f + erff(h * 0.70710678118654752f));
        }
        __syncwarp();

        ull L0 = 0ull, L1 = 0ull;
#pragma unroll 4
        for (int e = 0; e < Em; e++) {
            ull a2 = pk2d(fs[GBUF_F + w * Hm + e]);
            ulonglong2 wd = *(const ulonglong2*)&fs[WDT_F + e * Hm + lane * 4];
            fma2(L0, a2, wd.x);
            fma2(L1, a2, wd.y);
        }
        float2 p0 = up2(L0), p1 = up2(L1);
        float lg[4] = {p0.x, p0.y, p1.x, p1.y};

        float4 gu = *(const float4*)&gumbel[(size_t)gt * Hm + lane * 4];
        float gua[4] = {gu.x, gu.y, gu.z, gu.w};

        float ap[4], bn[4];
        float csum = 0.f;
#pragma unroll
        for (int jj = 0; jj < 4; jj++) {
            float z = (lg[jj] + gua[jj] + 3.0f) * 2.5f;
            ap[jj] = 1.0f / (1.0f + expf(-z));
            bn[jj] = rintf(ap[jj]);
            csum += bn[jj];
        }
#pragma unroll
        for (int o = 16; o > 0; o >>= 1) csum += __shfl_xor_sync(0xffffffffu, csum, o);

        float ob[4];
        if (csum > Kf || csum == 0.0f) {
            const int kneed = (csum > Kf) ? K : 1;
#pragma unroll
            for (int jj = 0; jj < 4; jj++) fs[ABUF_F + w * Hm + lane * 4 + jj] = ap[jj];
            __syncwarp();
            int r[4] = {0, 0, 0, 0};
            for (int j4 = 0; j4 < Hm; j4 += 4) {
                float4 av = *(const float4*)&fs[ABUF_F + w * Hm + j4];
                float aj[4] = {av.x, av.y, av.z, av.w};
#pragma unroll
                for (int u = 0; u < 4; u++) {
                    int j = j4 + u;
#pragma unroll
                    for (int jj = 0; jj < 4; jj++) {
                        int idx = lane * 4 + jj;
                        r[jj] += (aj[u] > ap[jj]) || (aj[u] == ap[jj] && j < idx);
                    }
                }
            }
#pragma unroll
            for (int jj = 0; jj < 4; jj++) ob[jj] = (r[jj] < kneed) ? 1.0f : 0.0f;
            __syncwarp();
        } else {
#pragma unroll
            for (int jj = 0; jj < 4; jj++) ob[jj] = bn[jj];
        }

        *(float4*)&out_bin[(size_t)gt * Hm + lane * 4] = make_float4(ob[0], ob[1], ob[2], ob[3]);
        if (out_ap)
            *(float4*)&out_ap[(size_t)gt * Hm + lane * 4] = make_float4(ap[0], ap[1], ap[2], ap[3]);
    }
}

extern "C" void kernel_launch(void* const* d_in, const int* in_sizes, int n_in,
                              void* d_out, int out_size) {
    const float* x        = (const float*)d_in[0];
    const float* W_router = (const float*)d_in[1];
    const float* W_dec    = (const float*)d_in[2];
    const float* ln_gamma = (const float*)d_in[3];
    const float* ln_beta  = (const float*)d_in[4];
    const float* rnn      = (const float*)d_in[5];
    const float* gumbel   = (const float*)d_in[6];
    const int*   topk     = (const int*)d_in[7];

    float* out_bin = (float*)d_out;
    const size_t N = (size_t)TOKENS * Hm;
    float* out_ap = ((size_t)out_size >= 2 * N) ? out_bin + N : nullptr;

    prep_kernel<<<(Em * Dm) / 256, 256>>>(W_router, W_dec);

    cudaFuncSetAttribute(fused_kernel, cudaFuncAttributeMaxDynamicSharedMemorySize, SMEM_SZ);
    fused_kernel<<<TOKENS / MT, 256, SMEM_SZ>>>(
        x, gumbel, rnn, ln_gamma, ln_beta, topk, out_bin, out_ap);
}